// round 1
// baseline (speedup 1.0000x reference)
#include <cuda_runtime.h>
#include <cuda_bf16.h>
#include <math.h>

#define B_   32
#define N_   196
#define E_   512
#define H_   8
#define HD_  64
#define L_   4
#define M_   (B_*N_)          // 6272 tokens
#define PD_  3840             // patch dim
#define NCLS_ 101
#define EPS_ 1e-5f

// ---------------- scratch (device globals; no cudaMalloc allowed) ------------
__device__ float g_x1[M_*E_];
__device__ float g_x2[M_*E_];
__device__ float g_t[M_*E_];
__device__ float g_qkv[M_*3*E_];
__device__ float g_q[M_*E_];
__device__ float g_kv[M_*2*E_];
__device__ float g_sc[(size_t)B_*H_*N_*N_];
__device__ float g_ao[M_*E_];
__device__ float g_hid[M_*4*E_];
__device__ float g_patch[(size_t)M_*PD_];
__device__ float g_feat[B_*2*E_];
__device__ float g_clsh[B_*4*E_];

// ---------------- generic GEMM:  C = act(A(M,K) @ W(N,K)^T + bias [+ res]) ---
#define BM 128
#define BN 64
#define BK 16

__global__ void gemm_kernel(const float* __restrict__ A,
                            const float* __restrict__ W,
                            const float* __restrict__ bias,
                            const float* __restrict__ res,
                            float* __restrict__ C,
                            int M, int N, int K, int relu)
{
    __shared__ float As[BK][BM+4];
    __shared__ float Ws[BK][BN+4];
    int tid = threadIdx.x;
    int tx = tid & 15;          // 16 col-groups of 4
    int ty = tid >> 4;          // 16 row-groups of 8
    int m0 = blockIdx.y * BM;
    int n0 = blockIdx.x * BN;
    float acc[8][4];
#pragma unroll
    for (int i = 0; i < 8; i++)
#pragma unroll
        for (int j = 0; j < 4; j++) acc[i][j] = 0.f;

    for (int k0 = 0; k0 < K; k0 += BK) {
#pragma unroll
        for (int t = 0; t < 2; t++) {           // A tile: 128x16 = 512 float4
            int f = tid + t * 256;
            int r = f >> 2, kq = (f & 3) << 2;
            int m = m0 + r;
            float4 v = make_float4(0.f,0.f,0.f,0.f);
            if (m < M) v = *reinterpret_cast<const float4*>(A + (size_t)m*K + k0 + kq);
            As[kq][r]   = v.x; As[kq+1][r] = v.y;
            As[kq+2][r] = v.z; As[kq+3][r] = v.w;
        }
        {                                        // W tile: 64x16 = 256 float4
            int r = tid >> 2, kq = (tid & 3) << 2;
            int n = n0 + r;
            float4 v = make_float4(0.f,0.f,0.f,0.f);
            if (n < N) v = *reinterpret_cast<const float4*>(W + (size_t)n*K + k0 + kq);
            Ws[kq][r]   = v.x; Ws[kq+1][r] = v.y;
            Ws[kq+2][r] = v.z; Ws[kq+3][r] = v.w;
        }
        __syncthreads();
#pragma unroll
        for (int kk = 0; kk < BK; kk++) {
            float4 a0 = *reinterpret_cast<const float4*>(&As[kk][ty*8]);
            float4 a1 = *reinterpret_cast<const float4*>(&As[kk][ty*8+4]);
            float4 b0 = *reinterpret_cast<const float4*>(&Ws[kk][tx*4]);
            float a[8] = {a0.x,a0.y,a0.z,a0.w,a1.x,a1.y,a1.z,a1.w};
            float b[4] = {b0.x,b0.y,b0.z,b0.w};
#pragma unroll
            for (int i = 0; i < 8; i++)
#pragma unroll
                for (int j = 0; j < 4; j++)
                    acc[i][j] += a[i]*b[j];
        }
        __syncthreads();
    }
#pragma unroll
    for (int i = 0; i < 8; i++) {
        int m = m0 + ty*8 + i;
        if (m >= M) continue;
#pragma unroll
        for (int j = 0; j < 4; j++) {
            int n = n0 + tx*4 + j;
            if (n >= N) continue;
            float v = acc[i][j] + bias[n];
            if (res) v += res[(size_t)m*N + n];
            if (relu) v = fmaxf(v, 0.f);
            C[(size_t)m*N + n] = v;
        }
    }
}

// ---------------- LayerNorm over 512 ----------------------------------------
__global__ void ln_kernel(const float* __restrict__ x,
                          const float* __restrict__ g,
                          const float* __restrict__ b,
                          float* __restrict__ y)
{
    int row = blockIdx.x;
    const float* xr = x + (size_t)row * E_;
    int tid = threadIdx.x;
    float v0 = xr[tid], v1 = xr[tid + 256];
    float s  = v0 + v1;
    float ss = v0*v0 + v1*v1;
#pragma unroll
    for (int o = 16; o > 0; o >>= 1) {
        s  += __shfl_xor_sync(0xffffffffu, s,  o);
        ss += __shfl_xor_sync(0xffffffffu, ss, o);
    }
    __shared__ float sh[16];
    int w = tid >> 5, lane = tid & 31;
    if (lane == 0) { sh[w] = s; sh[8+w] = ss; }
    __syncthreads();
    if (tid == 0) {
        float a = 0.f, c = 0.f;
        for (int i = 0; i < 8; i++) { a += sh[i]; c += sh[8+i]; }
        sh[0] = a; sh[8] = c;
    }
    __syncthreads();
    float mean = sh[0] * (1.f/E_);
    float var  = sh[8] * (1.f/E_) - mean*mean;
    float rs = rsqrtf(var + EPS_);
    float* yr = y + (size_t)row * E_;
    yr[tid]       = (v0 - mean) * rs * g[tid]       + b[tid];
    yr[tid + 256] = (v1 - mean) * rs * g[tid + 256] + b[tid + 256];
}

// ---------------- shifted-patch gather + LN(3840) ----------------------------
__global__ void patch_ln_kernel(const float* __restrict__ image,
                                const float* __restrict__ g,
                                const float* __restrict__ bb)
{
    __shared__ float buf[PD_];
    __shared__ float sh[16];
    int bn = blockIdx.x;
    int b  = bn / N_, n = bn % N_;
    int ph = n / 14, pw = n % 14;
    int tid = threadIdx.x;

    float s = 0.f, ss = 0.f;
    for (int d = tid; d < PD_; d += 256) {
        int c  = d % 15, t = d / 15;
        int p2 = t % 16, p1 = t / 16;
        int sh_idx = c / 3, ch = c % 3;
        int row = ph*16 + p1, col = pw*16 + p2;
        if      (sh_idx == 1) col -= 1;
        else if (sh_idx == 2) col += 1;
        else if (sh_idx == 3) row -= 1;
        else if (sh_idx == 4) row += 1;
        float v = 0.f;
        if (row >= 0 && row < 224 && col >= 0 && col < 224)
            v = image[(((size_t)b*3 + ch)*224 + row)*224 + col];
        buf[d] = v;
        s += v; ss += v*v;
    }
#pragma unroll
    for (int o = 16; o > 0; o >>= 1) {
        s  += __shfl_xor_sync(0xffffffffu, s,  o);
        ss += __shfl_xor_sync(0xffffffffu, ss, o);
    }
    int w = tid >> 5, lane = tid & 31;
    if (lane == 0) { sh[w] = s; sh[8+w] = ss; }
    __syncthreads();
    if (tid == 0) {
        float a = 0.f, c = 0.f;
        for (int i = 0; i < 8; i++) { a += sh[i]; c += sh[8+i]; }
        sh[0] = a; sh[8] = c;
    }
    __syncthreads();
    float mean = sh[0] * (1.f/PD_);
    float var  = sh[8] * (1.f/PD_) - mean*mean;
    float rs = rsqrtf(var + EPS_);
    float* out = g_patch + (size_t)bn * PD_;
    for (int d = tid; d < PD_; d += 256)
        out[d] = (buf[d] - mean) * rs * g[d] + bb[d];
}

// ---------------- positional add (buggy batch-indexed sinusoid, per ref) -----
__global__ void posadd_kernel()
{
    int idx = blockIdx.x * 256 + threadIdx.x;
    if (idx >= M_*E_) return;
    int e = idx & (E_-1);
    int b = idx / (N_*E_);
    float p = (float)(b + 1);
    int i = e & 255;
    float f = expf(-(float)i * (9.210340371976184f / 255.0f));
    float ang = p * f;
    float v = (e < 256) ? sinf(ang) : cosf(ang);
    g_x1[idx] += v;
    g_x2[idx] += v;
}

// ---------------- attention: scores = scale * Q K^T --------------------------
__global__ void scores_kernel(const float* __restrict__ Qp,
                              const float* __restrict__ Kp,
                              int qstride, int kstride, float scale)
{
    int bh = blockIdx.z;
    int b = bh >> 3, h = bh & 7;
    int q0 = blockIdx.y * 16, k0 = blockIdx.x * 16;
    __shared__ float qs[16][68];
    __shared__ float ks[16][68];
    int tid = threadIdx.x;
    int r = tid >> 4, c4 = (tid & 15) * 4;
    {
        int q = q0 + r;
        float4 v = make_float4(0.f,0.f,0.f,0.f);
        if (q < N_) v = *reinterpret_cast<const float4*>(Qp + (size_t)(b*N_+q)*qstride + h*HD_ + c4);
        qs[r][c4]=v.x; qs[r][c4+1]=v.y; qs[r][c4+2]=v.z; qs[r][c4+3]=v.w;
        int k = k0 + r;
        float4 w = make_float4(0.f,0.f,0.f,0.f);
        if (k < N_) w = *reinterpret_cast<const float4*>(Kp + (size_t)(b*N_+k)*kstride + h*HD_ + c4);
        ks[r][c4]=w.x; ks[r][c4+1]=w.y; ks[r][c4+2]=w.z; ks[r][c4+3]=w.w;
    }
    __syncthreads();
    int ty = tid >> 4, tx = tid & 15;
    float s = 0.f;
#pragma unroll
    for (int d = 0; d < HD_; d++) s += qs[ty][d] * ks[tx][d];
    int q = q0 + ty, k = k0 + tx;
    if (q < N_ && k < N_)
        g_sc[((size_t)bh*N_ + q)*N_ + k] = s * scale;
}

// ---------------- row softmax over 196 ---------------------------------------
__global__ void softmax_kernel()
{
    int gw = (blockIdx.x * blockDim.x + threadIdx.x) >> 5;
    if (gw >= B_*H_*N_) return;
    int lane = threadIdx.x & 31;
    float* row = g_sc + (size_t)gw * N_;
    float vals[7];
    float mx = -1e30f;
#pragma unroll
    for (int i = 0; i < 7; i++) {
        int j = lane + 32*i;
        vals[i] = (j < N_) ? row[j] : -1e30f;
        mx = fmaxf(mx, vals[i]);
    }
#pragma unroll
    for (int o = 16; o > 0; o >>= 1) mx = fmaxf(mx, __shfl_xor_sync(0xffffffffu, mx, o));
    float sum = 0.f;
#pragma unroll
    for (int i = 0; i < 7; i++) { vals[i] = expf(vals[i] - mx); sum += vals[i]; }
#pragma unroll
    for (int o = 16; o > 0; o >>= 1) sum += __shfl_xor_sync(0xffffffffu, sum, o);
    float inv = 1.f / sum;
#pragma unroll
    for (int i = 0; i < 7; i++) {
        int j = lane + 32*i;
        if (j < N_) row[j] = vals[i] * inv;
    }
}

// ---------------- PV: Out[b,q,h*64+d] = sum_k P[bh,q,k] V[b,k,h*64+d] --------
__global__ void pv_kernel(const float* __restrict__ Vp, int vstride,
                          float* __restrict__ Out)
{
    int bh = blockIdx.y;
    int b = bh >> 3, h = bh & 7;
    int q0 = blockIdx.x * 32;
    __shared__ float Ps[32][17];
    __shared__ float Vs[16][64];
    int tid = threadIdx.x;
    int tx = tid & 63, ty = tid >> 6;
    float acc[8];
#pragma unroll
    for (int i = 0; i < 8; i++) acc[i] = 0.f;

    for (int k0 = 0; k0 < N_; k0 += 16) {
        {
            int pr = tid >> 3, pc = (tid & 7) * 2;
#pragma unroll
            for (int j = 0; j < 2; j++) {
                int q = q0 + pr, k = k0 + pc + j;
                Ps[pr][pc+j] = (q < N_ && k < N_) ? g_sc[((size_t)bh*N_+q)*N_ + k] : 0.f;
            }
        }
        {
            int vr = tid >> 4, vc = (tid & 15) * 4;
            int k = k0 + vr;
            float4 v = make_float4(0.f,0.f,0.f,0.f);
            if (k < N_) v = *reinterpret_cast<const float4*>(Vp + (size_t)(b*N_+k)*vstride + h*HD_ + vc);
            Vs[vr][vc]=v.x; Vs[vr][vc+1]=v.y; Vs[vr][vc+2]=v.z; Vs[vr][vc+3]=v.w;
        }
        __syncthreads();
#pragma unroll
        for (int kk = 0; kk < 16; kk++) {
            float vv = Vs[kk][tx];
#pragma unroll
            for (int i = 0; i < 8; i++)
                acc[i] += Ps[ty + 4*i][kk] * vv;
        }
        __syncthreads();
    }
#pragma unroll
    for (int i = 0; i < 8; i++) {
        int q = q0 + ty + 4*i;
        if (q < N_)
            Out[(size_t)(b*N_+q)*E_ + h*HD_ + tx] = acc[i];
    }
}

// ---------------- final LN of last token -> feat (B, 2E) ---------------------
__global__ void final_feat_kernel(const float* __restrict__ g,
                                  const float* __restrict__ b)
{
    int s = blockIdx.x >> 5;   // stream 0/1
    int bb = blockIdx.x & 31;  // batch
    const float* src = (s ? g_x2 : g_x1) + (size_t)(bb*N_ + (N_-1)) * E_;
    int tid = threadIdx.x;
    float v0 = src[tid], v1 = src[tid + 256];
    float ssum = v0 + v1, sq = v0*v0 + v1*v1;
#pragma unroll
    for (int o = 16; o > 0; o >>= 1) {
        ssum += __shfl_xor_sync(0xffffffffu, ssum, o);
        sq   += __shfl_xor_sync(0xffffffffu, sq,   o);
    }
    __shared__ float sh[16];
    int w = tid >> 5, lane = tid & 31;
    if (lane == 0) { sh[w] = ssum; sh[8+w] = sq; }
    __syncthreads();
    if (tid == 0) {
        float a = 0.f, c = 0.f;
        for (int i = 0; i < 8; i++) { a += sh[i]; c += sh[8+i]; }
        sh[0] = a; sh[8] = c;
    }
    __syncthreads();
    float mean = sh[0] * (1.f/E_);
    float var  = sh[8] * (1.f/E_) - mean*mean;
    float rs = rsqrtf(var + EPS_);
    float* dst = g_feat + (size_t)bb * (2*E_) + s*E_;
    dst[tid]       = (v0 - mean) * rs * g[tid]       + b[tid];
    dst[tid + 256] = (v1 - mean) * rs * g[tid + 256] + b[tid + 256];
}

// ---------------- host-side orchestration ------------------------------------
static inline void gemm(const float* A, const float* W, const float* bias,
                        const float* res, float* C, int M, int N, int K, int relu)
{
    dim3 grid((N + BN - 1)/BN, (M + BM - 1)/BM);
    gemm_kernel<<<grid, 256>>>(A, W, bias, res, C, M, N, K, relu);
}

extern "C" void kernel_launch(void* const* d_in, const int* in_sizes, int n_in,
                              void* d_out, int out_size)
{
    const float* image      = (const float*)d_in[0];
    const float* text_hidden= (const float*)d_in[1];
    const float* patch_ln_g = (const float*)d_in[2];
    const float* patch_ln_b = (const float*)d_in[3];
    const float* patch_w    = (const float*)d_in[4];
    const float* patch_b    = (const float*)d_in[5];
    const float* text_w     = (const float*)d_in[6];
    const float* text_b     = (const float*)d_in[7];
    const float* attn_in_w  = (const float*)d_in[8];
    const float* attn_in_b  = (const float*)d_in[9];
    const float* attn_out_w = (const float*)d_in[10];
    const float* attn_out_b = (const float*)d_in[11];
    const float* mlp_w1     = (const float*)d_in[12];
    const float* mlp_b1     = (const float*)d_in[13];
    const float* mlp_w2     = (const float*)d_in[14];
    const float* mlp_b2     = (const float*)d_in[15];
    const float* ln_gamma   = (const float*)d_in[16];
    const float* ln_beta    = (const float*)d_in[17];
    const float* fin_g      = (const float*)d_in[18];
    const float* fin_b      = (const float*)d_in[19];
    const float* cls_w1     = (const float*)d_in[20];
    const float* cls_b1     = (const float*)d_in[21];
    const float* cls_w2     = (const float*)d_in[22];
    const float* cls_b2     = (const float*)d_in[23];

    float *x1p,*x2p,*tp,*qkvp,*qp,*kvp,*aop,*hidp,*patchp,*featp,*clshp;
    cudaGetSymbolAddress((void**)&x1p,   g_x1);
    cudaGetSymbolAddress((void**)&x2p,   g_x2);
    cudaGetSymbolAddress((void**)&tp,    g_t);
    cudaGetSymbolAddress((void**)&qkvp,  g_qkv);
    cudaGetSymbolAddress((void**)&qp,    g_q);
    cudaGetSymbolAddress((void**)&kvp,   g_kv);
    cudaGetSymbolAddress((void**)&aop,   g_ao);
    cudaGetSymbolAddress((void**)&hidp,  g_hid);
    cudaGetSymbolAddress((void**)&patchp,g_patch);
    cudaGetSymbolAddress((void**)&featp, g_feat);
    cudaGetSymbolAddress((void**)&clshp, g_clsh);

    const float scale = 0.125f;  // 1/sqrt(64)
    dim3 sc_grid(13, 13, B_*H_);
    dim3 pv_grid(7, B_*H_);
    int sm_blocks = (B_*H_*N_*32 + 127) / 128;

    // --- embedding ---
    patch_ln_kernel<<<M_, 256>>>(image, patch_ln_g, patch_ln_b);
    gemm(patchp, patch_w, patch_b, nullptr, x1p, M_, E_, PD_, 0);
    gemm(text_hidden, text_w, text_b, nullptr, x2p, M_, E_, 768, 0);
    posadd_kernel<<<(M_*E_ + 255)/256, 256>>>();

    for (int l = 0; l < L_; l++) {
        const float* g0 = ln_gamma + (size_t)(l*2+0)*E_;
        const float* b0 = ln_beta  + (size_t)(l*2+0)*E_;
        const float* g1 = ln_gamma + (size_t)(l*2+1)*E_;
        const float* b1 = ln_beta  + (size_t)(l*2+1)*E_;

        // --- self-attention, both streams ---
        for (int s = 0; s < 2; s++) {
            float* xp = s ? x2p : x1p;
            const float* wi = attn_in_w  + (size_t)(l*3+s)*1536*E_;
            const float* bi = attn_in_b  + (size_t)(l*3+s)*1536;
            const float* wo = attn_out_w + (size_t)(l*3+s)*E_*E_;
            const float* bo = attn_out_b + (size_t)(l*3+s)*E_;
            ln_kernel<<<M_, 256>>>(xp, g0, b0, tp);
            gemm(tp, wi, bi, nullptr, qkvp, M_, 1536, E_, 0);
            scores_kernel<<<sc_grid, 256>>>(qkvp, qkvp + E_, 1536, 1536, scale);
            softmax_kernel<<<sm_blocks, 128>>>();
            pv_kernel<<<pv_grid, 256>>>(qkvp + 2*E_, 1536, aop);
            gemm(aop, wo, bo, xp, xp, M_, E_, E_, 0);
        }

        // --- guide attention: q from x2, kv from x1, overwrites x1 ---
        {
            const float* wi = attn_in_w  + (size_t)(l*3+2)*1536*E_;
            const float* bi = attn_in_b  + (size_t)(l*3+2)*1536;
            const float* wo = attn_out_w + (size_t)(l*3+2)*E_*E_;
            const float* bo = attn_out_b + (size_t)(l*3+2)*E_;
            gemm(x2p, wi, bi, nullptr, qp, M_, E_, E_, 0);                         // Q
            gemm(x1p, wi + (size_t)E_*E_, bi + E_, nullptr, kvp, M_, 2*E_, E_, 0); // K,V
            scores_kernel<<<sc_grid, 256>>>(qp, kvp, E_, 2*E_, scale);
            softmax_kernel<<<sm_blocks, 128>>>();
            pv_kernel<<<pv_grid, 256>>>(kvp + E_, 2*E_, aop);
            gemm(aop, wo, bo, nullptr, x1p, M_, E_, E_, 0);
        }

        // --- MLP, both streams (shared weights) ---
        const float* w1 = mlp_w1 + (size_t)l*4*E_*E_;
        const float* bb1 = mlp_b1 + (size_t)l*4*E_;
        const float* w2 = mlp_w2 + (size_t)l*E_*4*E_;
        const float* bb2 = mlp_b2 + (size_t)l*E_;
        for (int s = 0; s < 2; s++) {
            float* xp = s ? x2p : x1p;
            ln_kernel<<<M_, 256>>>(xp, g1, b1, tp);
            gemm(tp, w1, bb1, nullptr, hidp, M_, 4*E_, E_, 1);
            gemm(hidp, w2, bb2, xp, xp, M_, E_, 4*E_, 0);
        }
    }

    // --- head ---
    final_feat_kernel<<<64, 256>>>(fin_g, fin_b);
    gemm(featp, cls_w1, cls_b1, nullptr, clshp, B_, 4*E_, 2*E_, 1);
    gemm(clshp, cls_w2, cls_b2, nullptr, (float*)d_out, B_, NCLS_, 4*E_, 0);
}